// round 16
// baseline (speedup 1.0000x reference)
#include <cuda_runtime.h>

// Problem shape (fixed by the dataset)
constexpr int Bsz = 256;
constexpr int Lsz = 65536;
constexpr int Tc  = 128;          // samples per chunk (per thread)
constexpr int Cc  = Lsz / Tc;     // 512 chunks per row = threads per block
constexpr int NW  = Cc / 32;      // 16 warps per block
constexpr int NS  = 8;            // sections per chunk
constexpr int SEC = Tc / NS;      // 16 samples per section
constexpr int SF4 = SEC / 4;      // 4 float4 per section per chunk
constexpr int PITCH = SF4 + 1;    // smem pitch in float4 (5 -> conflict-free)
constexpr int SMEM_DYN = Cc * PITCH * 16;   // 40960 bytes

// Paul Kellet pink filter coefficients
constexpr float A0 = 0.99886f, A1 = 0.99332f, A2 = 0.969f,
                A3 = 0.8665f,  A4 = 0.55f,    A5 = -0.7616f;
constexpr float C0c = 0.0555179f, C1c = 0.0750759f, C2c = 0.153852f,
                C3c = 0.3104856f, C4c = 0.5329522f, C5c = -0.016898f;
constexpr float DIRECT = 0.5362f, OUT_GAIN = 0.11f, B6_GAIN = 0.115926f;
constexpr float OGD = OUT_GAIN * DIRECT;
constexpr float OGB = OUT_GAIN * B6_GAIN;
// output-dot coefficients on the SCALED states r_p = s_p / C_p
constexpr float D0 = OUT_GAIN * C0c, D1 = OUT_GAIN * C1c, D2 = OUT_GAIN * C2c,
                D3 = OUT_GAIN * C3c, D4 = OUT_GAIN * C4c, D5 = OUT_GAIN * C5c;

// Flush-to-zero guard: nvcc's constexpr evaluator hard-errors on FP underflow.
constexpr double ftz(double x) {
    return (x < 1e-100 && x > -1e-100) ? 0.0 : x;
}
constexpr double cdpow(double a, long long n) {
    double r = 1.0, p = a;
    while (n > 0) {
        if (n & 1) r = ftz(r * p);
        p = ftz(p * p);
        n >>= 1;
    }
    return r;
}
constexpr float cpowf(double a, long long n) {
    double r = cdpow(a, n);
    if (r < 1e-37 && r > -1e-37) return 0.0f;
    return (float)r;
}

// Scan weight tables (device memory space required: plain constexpr arrays are
// host-only without --expt-relaxed-constexpr).
#define WARR(A) { cpowf(A,(long long)Tc), cpowf(A,(long long)Tc*2), cpowf(A,(long long)Tc*4), \
                  cpowf(A,(long long)Tc*8), cpowf(A,(long long)Tc*16) }
#define XARR(A) { cpowf(A,(long long)Tc*32), cpowf(A,(long long)Tc*64), \
                  cpowf(A,(long long)Tc*128), cpowf(A,(long long)Tc*256) }
__device__ __constant__ float W_[6][5] =
    { WARR(A0), WARR(A1), WARR(A2), WARR(A3), WARR(A4), WARR(A5) };
__device__ __constant__ float X_[6][4] =
    { XARR(A0), XARR(A1), XARR(A2), XARR(A3), XARR(A4), XARR(A5) };
__device__ __constant__ float M_[6] =
    { cpowf(A0,Tc), cpowf(A1,Tc), cpowf(A2,Tc),
      cpowf(A3,Tc), cpowf(A4,Tc), cpowf(A5,Tc) };

// float binary pow, n in [1, 32]
__device__ __forceinline__ float fpow6(float m, int n) {
    float r = 1.f, p = m;
#pragma unroll
    for (int i = 0; i < 6; ++i) { if (n & 1) r *= p; p *= p; n >>= 1; }
    return r;
}

// Scaled-state pole update: r_p = A_p * r_p + x  (literal A -> FFMA-imm, rt=1)
#define POLES_STEP(x)                      \
    {                                      \
        r0 = fmaf(A0, r0, (x));            \
        r1 = fmaf(A1, r1, (x));            \
        r2 = fmaf(A2, r2, (x));            \
        r3 = fmaf(A3, r3, (x));            \
        r4 = fmaf(A4, r4, (x));            \
        r5 = fmaf(A5, r5, (x));            \
    }

// ---------------------------------------------------------------------------
// One block per row (512 threads, target 3 blocks/SM). Streaming phases stage
// through a padded smem tile so all global traffic is coalesced:
//   per section: coalesced LDG -> STS -> conflict-free LDS -> IIR
// Phase 3 additionally computes in place in smem and stores coalesced.
// ---------------------------------------------------------------------------
__global__ void __launch_bounds__(Cc, 3) k_pink(const float* __restrict__ white,
                                                float* __restrict__ pink) {
    extern __shared__ float4 sbuf[];        // [Cc][PITCH] float4

    const int b = blockIdx.x;
    const int k = threadIdx.x;              // chunk index within row
    const int lane = k & 31, wid = k >> 5;
    const int cbase = k >> 2;               // staging: base chunk (0..127)
    const int f = k & 3;                    // staging: float4 index in section

    const float4* wrow = reinterpret_cast<const float4*>(white + (size_t)b * Lsz);
    float4* prow = reinterpret_cast<float4*>(pink + (size_t)b * Lsz);
    // chunk c, section s, float4 q -> global float4 index c*(Tc/4) + s*SF4 + q

    // ---- Phase 1: local scaled pole states, zero init, smem-staged
    float r0 = 0.f, r1 = 0.f, r2 = 0.f, r3 = 0.f, r4 = 0.f, r5 = 0.f;
    {
        float4 regs[4];
#pragma unroll
        for (int r = 0; r < 4; ++r)
            regs[r] = wrow[(cbase + 128 * r) * (Tc / 4) + f];         // s=0

        for (int s = 0; s < NS; ++s) {
#pragma unroll
            for (int r = 0; r < 4; ++r)
                sbuf[(cbase + 128 * r) * PITCH + f] = regs[r];
            __syncthreads();
            if (s + 1 < NS) {
#pragma unroll
                for (int r = 0; r < 4; ++r)
                    regs[r] = wrow[(cbase + 128 * r) * (Tc / 4) + (s + 1) * SF4 + f];
            }
#pragma unroll
            for (int q = 0; q < SF4; ++q) {
                const float4 w = sbuf[k * PITCH + q];
                POLES_STEP(w.x) POLES_STEP(w.y) POLES_STEP(w.z) POLES_STEP(w.w)
            }
            __syncthreads();
        }
    }

    // ---- Phase 2: inclusive scan I(k) = sum_{j<=k} M^(k-j) local(j)
    float v[6] = {r0, r1, r2, r3, r4, r5};

#pragma unroll
    for (int j = 0; j < 5; ++j) {
        const int d = 1 << j;
        float u[6];
#pragma unroll
        for (int p = 0; p < 6; ++p) u[p] = __shfl_up_sync(0xffffffffu, v[p], d);
        if (lane >= d)
#pragma unroll
            for (int p = 0; p < 6; ++p) v[p] = fmaf(W_[p][j], u[p], v[p]);
    }

    __shared__ float tot[NW][6];
    __shared__ float pre[NW][6];
    if (lane == 31)
#pragma unroll
        for (int p = 0; p < 6; ++p) tot[wid][p] = v[p];
    __syncthreads();

    if (wid == 0) {
        float t[6];
#pragma unroll
        for (int p = 0; p < 6; ++p) t[p] = (lane < NW) ? tot[lane][p] : 0.f;
#pragma unroll
        for (int j = 0; j < 4; ++j) {
            const int d = 1 << j;
            float u[6];
#pragma unroll
            for (int p = 0; p < 6; ++p) u[p] = __shfl_up_sync(0xffffffffu, t[p], d);
            if (lane >= d)
#pragma unroll
                for (int p = 0; p < 6; ++p) t[p] = fmaf(X_[p][j], u[p], t[p]);
        }
#pragma unroll
        for (int p = 0; p < 6; ++p) {
            float e = __shfl_up_sync(0xffffffffu, t[p], 1);
            if (lane == 0) e = 0.f;
            if (lane < NW) pre[lane][p] = e;
        }
    }
    __syncthreads();

    float pw[6];
#pragma unroll
    for (int p = 0; p < 6; ++p) pw[p] = pre[wid][p];
#pragma unroll
    for (int p = 0; p < 6; ++p) {
        float lf = fpow6(M_[p], lane + 1);
        v[p] = fmaf(lf, pw[p], v[p]);
    }

    float ini[6];
#pragma unroll
    for (int p = 0; p < 6; ++p) {
        float u = __shfl_up_sync(0xffffffffu, v[p], 1);
        ini[p] = (lane == 0) ? pw[p] : u;
    }

    // ---- Phase 3: re-run chunk from exact init, smem-staged both ways
    float xprev = (k > 0) ? white[(size_t)b * Lsz + (size_t)k * Tc - 1] : 0.f;
    r0 = ini[0]; r1 = ini[1]; r2 = ini[2];
    r3 = ini[3]; r4 = ini[4]; r5 = ini[5];

    {
        float4 regs[4];
#pragma unroll
        for (int r = 0; r < 4; ++r)
            regs[r] = wrow[(cbase + 128 * r) * (Tc / 4) + f];         // s=0

        for (int s = 0; s < NS; ++s) {
#pragma unroll
            for (int r = 0; r < 4; ++r)
                sbuf[(cbase + 128 * r) * PITCH + f] = regs[r];
            __syncthreads();
            if (s + 1 < NS) {
#pragma unroll
                for (int r = 0; r < 4; ++r)
                    regs[r] = wrow[(cbase + 128 * r) * (Tc / 4) + (s + 1) * SF4 + f];
            }
            // compute in place: consume w, write y
#pragma unroll
            for (int q = 0; q < SF4; ++q) {
                const float4 w = sbuf[k * PITCH + q];
                float xs[4] = {w.x, w.y, w.z, w.w};
                float ys[4];
#pragma unroll
                for (int i = 0; i < 4; ++i) {
                    const float x = xs[i];
                    POLES_STEP(x)
                    float acc = fmaf(OGD, x, OGB * xprev);
                    acc = fmaf(D0, r0, acc);
                    acc = fmaf(D1, r1, acc);
                    acc = fmaf(D2, r2, acc);
                    acc = fmaf(D3, r3, acc);
                    acc = fmaf(D4, r4, acc);
                    ys[i] = fmaf(D5, r5, acc);
                    xprev = x;
                }
                float4 o;
                o.x = ys[0]; o.y = ys[1]; o.z = ys[2]; o.w = ys[3];
                sbuf[k * PITCH + q] = o;
            }
            __syncthreads();
            // coalesced store of the section
#pragma unroll
            for (int r = 0; r < 4; ++r)
                prow[(cbase + 128 * r) * (Tc / 4) + s * SF4 + f] =
                    sbuf[(cbase + 128 * r) * PITCH + f];
            __syncthreads();
        }
    }
}

// ---------------------------------------------------------------------------
extern "C" void kernel_launch(void* const* d_in, const int* in_sizes, int n_in,
                              void* d_out, int out_size) {
    const float* white = (const float*)d_in[0];
    float* pink = (float*)d_out;
    (void)in_sizes; (void)n_in; (void)out_size;

    cudaFuncSetAttribute(k_pink, cudaFuncAttributeMaxDynamicSharedMemorySize,
                         SMEM_DYN);
    k_pink<<<Bsz, Cc, SMEM_DYN>>>(white, pink);
}

// round 17
// speedup vs baseline: 1.3209x; 1.3209x over previous
#include <cuda_runtime.h>

// Problem shape (fixed by the dataset)
constexpr int Bsz = 256;
constexpr int Lsz = 65536;
constexpr int Tc  = 128;          // samples per chunk (per thread)
constexpr int Cc  = Lsz / Tc;     // 512 chunks per row = threads per block
constexpr int NW  = Cc / 32;      // 16 warps per block
constexpr int NS  = 4;            // sections per chunk
constexpr int SEC = Tc / NS;      // 32 samples per section
constexpr int SF4 = SEC / 4;      // 8 float4 per section per chunk
constexpr int PITCH = SF4 + 1;    // warp-tile pitch in float4 (9 -> conflict-free)
constexpr int TILE_F4 = 32 * PITCH;           // float4 per warp tile
constexpr int SMEM_DYN = NW * TILE_F4 * 16;   // 73728 bytes

// Paul Kellet pink filter coefficients
constexpr float A0 = 0.99886f, A1 = 0.99332f, A2 = 0.969f,
                A3 = 0.8665f,  A4 = 0.55f,    A5 = -0.7616f;
constexpr float C0c = 0.0555179f, C1c = 0.0750759f, C2c = 0.153852f,
                C3c = 0.3104856f, C4c = 0.5329522f, C5c = -0.016898f;
constexpr float DIRECT = 0.5362f, OUT_GAIN = 0.11f, B6_GAIN = 0.115926f;
constexpr float OGD = OUT_GAIN * DIRECT;
constexpr float OGB = OUT_GAIN * B6_GAIN;
// output-dot coefficients on the SCALED states r_p = s_p / C_p
constexpr float D0 = OUT_GAIN * C0c, D1 = OUT_GAIN * C1c, D2 = OUT_GAIN * C2c,
                D3 = OUT_GAIN * C3c, D4 = OUT_GAIN * C4c, D5 = OUT_GAIN * C5c;

// Flush-to-zero guard: nvcc's constexpr evaluator hard-errors on FP underflow.
constexpr double ftz(double x) {
    return (x < 1e-100 && x > -1e-100) ? 0.0 : x;
}
constexpr double cdpow(double a, long long n) {
    double r = 1.0, p = a;
    while (n > 0) {
        if (n & 1) r = ftz(r * p);
        p = ftz(p * p);
        n >>= 1;
    }
    return r;
}
constexpr float cpowf(double a, long long n) {
    double r = cdpow(a, n);
    if (r < 1e-37 && r > -1e-37) return 0.0f;
    return (float)r;
}

// Scan weight tables (device memory space required: plain constexpr arrays are
// host-only without --expt-relaxed-constexpr).
#define WARR(A) { cpowf(A,(long long)Tc), cpowf(A,(long long)Tc*2), cpowf(A,(long long)Tc*4), \
                  cpowf(A,(long long)Tc*8), cpowf(A,(long long)Tc*16) }
#define XARR(A) { cpowf(A,(long long)Tc*32), cpowf(A,(long long)Tc*64), \
                  cpowf(A,(long long)Tc*128), cpowf(A,(long long)Tc*256) }
__device__ __constant__ float W_[6][5] =
    { WARR(A0), WARR(A1), WARR(A2), WARR(A3), WARR(A4), WARR(A5) };
__device__ __constant__ float X_[6][4] =
    { XARR(A0), XARR(A1), XARR(A2), XARR(A3), XARR(A4), XARR(A5) };
__device__ __constant__ float M_[6] =
    { cpowf(A0,Tc), cpowf(A1,Tc), cpowf(A2,Tc),
      cpowf(A3,Tc), cpowf(A4,Tc), cpowf(A5,Tc) };

// float binary pow, n in [1, 32]
__device__ __forceinline__ float fpow6(float m, int n) {
    float r = 1.f, p = m;
#pragma unroll
    for (int i = 0; i < 6; ++i) { if (n & 1) r *= p; p *= p; n >>= 1; }
    return r;
}

// Scaled-state pole update: r_p = A_p * r_p + x  (literal A -> FFMA-imm, rt=1)
#define POLES_STEP(x)                      \
    {                                      \
        r0 = fmaf(A0, r0, (x));            \
        r1 = fmaf(A1, r1, (x));            \
        r2 = fmaf(A2, r2, (x));            \
        r3 = fmaf(A3, r3, (x));            \
        r4 = fmaf(A4, r4, (x));            \
        r5 = fmaf(A5, r5, (x));            \
    }

// ---------------------------------------------------------------------------
// One block per row (512 threads). Warp-private staging: each warp owns the 32
// adjacent chunks of its 32 lanes and transposes coalesced<->sequential in its
// own padded smem tile with __syncwarp() only — NO block barriers in the
// streaming phases, so warps are fully decoupled and hide latency freely.
// ---------------------------------------------------------------------------
__global__ void __launch_bounds__(Cc, 2) k_pink(const float* __restrict__ white,
                                                float* __restrict__ pink) {
    extern __shared__ float4 sbuf[];        // NW warp tiles, [32][PITCH] float4

    const int b = blockIdx.x;
    const int k = threadIdx.x;              // chunk index within row
    const int lane = k & 31, wid = k >> 5;
    float4* tile = sbuf + wid * TILE_F4;
    const int rsub = lane >> 3;             // chunk sub-row within a load iter
    const int f = lane & 7;                 // float4 index within section

    const float4* wrow = reinterpret_cast<const float4*>(white + (size_t)b * Lsz);
    float4* prow = reinterpret_cast<float4*>(pink + (size_t)b * Lsz);
    // chunk c, section s, float4 q -> global float4 index c*(Tc/4) + s*SF4 + q
    // warp w covers chunks [w*32, w*32+32); load iter i covers chunks 4i..4i+3

    // ---- Phase 1: local scaled pole states, zero init, warp-staged
    float r0 = 0.f, r1 = 0.f, r2 = 0.f, r3 = 0.f, r4 = 0.f, r5 = 0.f;
    {
        float4 regs[8];
#pragma unroll
        for (int i = 0; i < 8; ++i)
            regs[i] = wrow[(wid * 32 + 4 * i + rsub) * (Tc / 4) + f];     // s=0

        for (int s = 0; s < NS; ++s) {
#pragma unroll
            for (int i = 0; i < 8; ++i)
                tile[(4 * i + rsub) * PITCH + f] = regs[i];
            __syncwarp();
            if (s + 1 < NS) {
#pragma unroll
                for (int i = 0; i < 8; ++i)
                    regs[i] = wrow[(wid * 32 + 4 * i + rsub) * (Tc / 4)
                                   + (s + 1) * SF4 + f];
            }
#pragma unroll
            for (int q = 0; q < SF4; ++q) {
                const float4 w = tile[lane * PITCH + q];
                POLES_STEP(w.x) POLES_STEP(w.y) POLES_STEP(w.z) POLES_STEP(w.w)
            }
            __syncwarp();
        }
    }

    // ---- Phase 2: inclusive scan I(k) = sum_{j<=k} M^(k-j) local(j)
    float v[6] = {r0, r1, r2, r3, r4, r5};

#pragma unroll
    for (int j = 0; j < 5; ++j) {
        const int d = 1 << j;
        float u[6];
#pragma unroll
        for (int p = 0; p < 6; ++p) u[p] = __shfl_up_sync(0xffffffffu, v[p], d);
        if (lane >= d)
#pragma unroll
            for (int p = 0; p < 6; ++p) v[p] = fmaf(W_[p][j], u[p], v[p]);
    }

    __shared__ float tot[NW][6];
    __shared__ float pre[NW][6];
    if (lane == 31)
#pragma unroll
        for (int p = 0; p < 6; ++p) tot[wid][p] = v[p];
    __syncthreads();

    if (wid == 0) {
        float t[6];
#pragma unroll
        for (int p = 0; p < 6; ++p) t[p] = (lane < NW) ? tot[lane][p] : 0.f;
#pragma unroll
        for (int j = 0; j < 4; ++j) {
            const int d = 1 << j;
            float u[6];
#pragma unroll
            for (int p = 0; p < 6; ++p) u[p] = __shfl_up_sync(0xffffffffu, t[p], d);
            if (lane >= d)
#pragma unroll
                for (int p = 0; p < 6; ++p) t[p] = fmaf(X_[p][j], u[p], t[p]);
        }
#pragma unroll
        for (int p = 0; p < 6; ++p) {
            float e = __shfl_up_sync(0xffffffffu, t[p], 1);
            if (lane == 0) e = 0.f;
            if (lane < NW) pre[lane][p] = e;
        }
    }
    __syncthreads();

    float pw[6];
#pragma unroll
    for (int p = 0; p < 6; ++p) pw[p] = pre[wid][p];
#pragma unroll
    for (int p = 0; p < 6; ++p) {
        float lf = fpow6(M_[p], lane + 1);
        v[p] = fmaf(lf, pw[p], v[p]);
    }

    float ini[6];
#pragma unroll
    for (int p = 0; p < 6; ++p) {
        float u = __shfl_up_sync(0xffffffffu, v[p], 1);
        ini[p] = (lane == 0) ? pw[p] : u;
    }

    // ---- Phase 3: re-run chunk from exact init, warp-staged both ways
    float xprev = (k > 0) ? white[(size_t)b * Lsz + (size_t)k * Tc - 1] : 0.f;
    r0 = ini[0]; r1 = ini[1]; r2 = ini[2];
    r3 = ini[3]; r4 = ini[4]; r5 = ini[5];

    {
        float4 regs[8];
#pragma unroll
        for (int i = 0; i < 8; ++i)
            regs[i] = wrow[(wid * 32 + 4 * i + rsub) * (Tc / 4) + f];     // s=0

        for (int s = 0; s < NS; ++s) {
#pragma unroll
            for (int i = 0; i < 8; ++i)
                tile[(4 * i + rsub) * PITCH + f] = regs[i];
            __syncwarp();
            if (s + 1 < NS) {
#pragma unroll
                for (int i = 0; i < 8; ++i)
                    regs[i] = wrow[(wid * 32 + 4 * i + rsub) * (Tc / 4)
                                   + (s + 1) * SF4 + f];
            }
            // compute in place in own tile row: consume w, write y
#pragma unroll
            for (int q = 0; q < SF4; ++q) {
                const float4 w = tile[lane * PITCH + q];
                float xs[4] = {w.x, w.y, w.z, w.w};
                float ys[4];
#pragma unroll
                for (int i = 0; i < 4; ++i) {
                    const float x = xs[i];
                    POLES_STEP(x)
                    float acc = fmaf(OGD, x, OGB * xprev);
                    acc = fmaf(D0, r0, acc);
                    acc = fmaf(D1, r1, acc);
                    acc = fmaf(D2, r2, acc);
                    acc = fmaf(D3, r3, acc);
                    acc = fmaf(D4, r4, acc);
                    ys[i] = fmaf(D5, r5, acc);
                    xprev = x;
                }
                float4 o;
                o.x = ys[0]; o.y = ys[1]; o.z = ys[2]; o.w = ys[3];
                tile[lane * PITCH + q] = o;
            }
            __syncwarp();
            // coalesced store of the section
#pragma unroll
            for (int i = 0; i < 8; ++i)
                prow[(wid * 32 + 4 * i + rsub) * (Tc / 4) + s * SF4 + f] =
                    tile[(4 * i + rsub) * PITCH + f];
            __syncwarp();
        }
    }
}

// ---------------------------------------------------------------------------
extern "C" void kernel_launch(void* const* d_in, const int* in_sizes, int n_in,
                              void* d_out, int out_size) {
    const float* white = (const float*)d_in[0];
    float* pink = (float*)d_out;
    (void)in_sizes; (void)n_in; (void)out_size;

    cudaFuncSetAttribute(k_pink, cudaFuncAttributeMaxDynamicSharedMemorySize,
                         SMEM_DYN);
    k_pink<<<Bsz, Cc, SMEM_DYN>>>(white, pink);
}